// round 5
// baseline (speedup 1.0000x reference)
#include <cuda_runtime.h>
#include <cuda_fp16.h>
#include <cstdint>
#include <math.h>

// ---------------------------------------------------------------------------
// Problem dims (fixed)
// ---------------------------------------------------------------------------
#define T_TOK 8192
#define H_DIM 2048
#define I_DIM 1408
#define E_NUM 32

#define SZ_X ((size_t)T_TOK * H_DIM)
#define SZ_HH ((size_t)T_TOK * I_DIM)

// Scratch (device globals — no allocations allowed anywhere).
__device__ __align__(256) __half g_x16[SZ_X];    // [T][H] fp16
__device__ __align__(256) __half g_h16[SZ_HH];   // [T][I] fp16

// ---------------------------------------------------------------------------
// PTX helpers (base-target legal: cp.async / ldmatrix / mma.sync)
// ---------------------------------------------------------------------------
__device__ __forceinline__ uint32_t smem_u32(const void* p) {
    uint32_t a;
    asm("{ .reg .u64 t; cvta.to.shared.u64 t, %1; cvt.u32.u64 %0, t; }"
        : "=r"(a) : "l"(p));
    return a;
}
__device__ __forceinline__ void cpa16(uint32_t s, const void* g) {
    asm volatile("cp.async.cg.shared.global [%0], [%1], 16;" :: "r"(s), "l"(g));
}
#define CP_COMMIT() asm volatile("cp.async.commit_group;" ::: "memory")
#define CP_WAIT1()  asm volatile("cp.async.wait_group 1;" ::: "memory")
#define CP_WAIT0()  asm volatile("cp.async.wait_group 0;" ::: "memory")

__device__ __forceinline__ void ldsm4(uint32_t* r, uint32_t addr) {
    asm volatile("ldmatrix.sync.aligned.m8n8.x4.shared.b16 {%0,%1,%2,%3}, [%4];"
                 : "=r"(r[0]), "=r"(r[1]), "=r"(r[2]), "=r"(r[3]) : "r"(addr));
}
__device__ __forceinline__ void ldsm4t(uint32_t* r, uint32_t addr) {
    asm volatile("ldmatrix.sync.aligned.m8n8.x4.trans.shared.b16 {%0,%1,%2,%3}, [%4];"
                 : "=r"(r[0]), "=r"(r[1]), "=r"(r[2]), "=r"(r[3]) : "r"(addr));
}
__device__ __forceinline__ void mma16816(float* d, const uint32_t* a,
                                         uint32_t b0, uint32_t b1) {
    asm volatile(
        "mma.sync.aligned.m16n8k16.row.col.f32.f16.f16.f32 "
        "{%0,%1,%2,%3}, {%4,%5,%6,%7}, {%8,%9}, {%0,%1,%2,%3};"
        : "+f"(d[0]), "+f"(d[1]), "+f"(d[2]), "+f"(d[3])
        : "r"(a[0]), "r"(a[1]), "r"(a[2]), "r"(a[3]), "r"(b0), "r"(b1));
}
__device__ __forceinline__ uint32_t pkh2(float a, float b) {
    __half2 h = __floats2half2_rn(a, b);
    return *reinterpret_cast<uint32_t*>(&h);
}

// ---------------------------------------------------------------------------
// Prologue: fp32 -> fp16 for x only (14us; weights convert inside the GEMMs)
// ---------------------------------------------------------------------------
__global__ __launch_bounds__(256)
void cvt_kernel(const float* __restrict__ src, __half* __restrict__ dst)
{
    size_t i = ((size_t)blockIdx.x * 256 + threadIdx.x) * 8;
    float4 v0 = *reinterpret_cast<const float4*>(src + i);
    float4 v1 = *reinterpret_cast<const float4*>(src + i + 4);
    uint4 o;
    o.x = pkh2(v0.x, v0.y);
    o.y = pkh2(v0.z, v0.w);
    o.z = pkh2(v1.x, v1.y);
    o.w = pkh2(v1.z, v1.w);
    *reinterpret_cast<uint4*>(dst + i) = o;
}

// ---------------------------------------------------------------------------
// Common tile machinery (CTA 128x128, BK=64, 8 warps = 4m x 2n, warp 32x64)
//
// A: fp16 [M,K] k-contig; cp.async straight into SW128-swizzled fp16 plane.
// B: fp32 [K,N] n-contig (NATIVE weight layout); cp.async into a linear fp32
//    staging plane, converted in-smem to a SW128 fp16 plane each k-iter.
//    fp16 B planes are double-buffered so convert(it+1) overlaps MMA(it).
// ---------------------------------------------------------------------------
#define APLANE 16384      // 128 x 64 fp16
#define BSTG32 32768      // 64 x 128 fp32 staging
#define BPLANE 16384      // 64 x 128 fp16 (two 64-n halves of 8KB)

__device__ __forceinline__ void prefetch_a(const __half* A, int K, int k0,
                                           uint32_t st, int tid) {
    #pragma unroll
    for (int p = 0; p < 4; p++) {
        int c   = tid + 256 * p;          // 0..1023
        int row = c >> 3;                 // m 0..127
        int kc  = c & 7;
        uint32_t so = (uint32_t)(row * 128 + ((kc ^ (row & 7)) << 4));
        cpa16(st + so, A + (size_t)row * K + k0 + kc * 8);
    }
}
// B fp32 tile [64 k][128 n] -> linear staging (row*512 + ch*16)
__device__ __forceinline__ void prefetch_b32(const float* B, int N, int k0,
                                             int n0, uint32_t st, int tid) {
    #pragma unroll
    for (int p = 0; p < 8; p++) {
        int c   = p * 256 + tid;          // 0..2047
        int row = c >> 5;                 // k 0..63
        int ch  = c & 31;                 // 16B chunk (4 floats)
        cpa16(st + (uint32_t)(row * 512 + ch * 16),
              B + (size_t)(k0 + row) * N + n0 + ch * 4);
    }
}
// In-smem convert: fp32 staging -> SW128 fp16 plane (8 float4 per thread)
__device__ __forceinline__ void convert_b(const char* stg, char* dst, int tid) {
    #pragma unroll
    for (int p = 0; p < 8; p++) {
        int c = p * 256 + tid;            // float4 index 0..2047
        int r = c >> 5;                   // k row
        int n = (c & 31) * 4;             // n col (mult of 4)
        float4 v = *reinterpret_cast<const float4*>(stg + c * 16);
        int half = n >> 6;
        int jj   = (n & 63) >> 3;
        uint32_t off = (uint32_t)(half * 8192 + r * 128 +
                                  ((jj ^ (r & 7)) << 4) + (n & 4) * 2);
        *reinterpret_cast<uint2*>(dst + off) =
            make_uint2(pkh2(v.x, v.y), pkh2(v.z, v.w));
    }
}
// B fragment smem offset (within one fp16 BPLANE) — proven in R4.
__device__ __forceinline__ uint32_t b_off(int s, int base_n, int lane) {
    int kRow = s * 16 + (lane & 7) + ((lane >> 4) << 3);
    int nOff = base_n + (((lane >> 3) & 1) << 3);
    int half = nOff >> 6;
    int jj   = (nOff & 63) >> 3;
    return (uint32_t)(half * 8192 + kRow * 128 + ((jj ^ (kRow & 7)) << 4));
}

// ---------------------------------------------------------------------------
// GEMM1: fused gate+up with in-kernel weight convert.
// smem: 2 stages x (A16 16K | Sg32 32K | Su32 32K) = 160K, then
//       Bg16[2] 32K | Bu16[2] 32K  -> total 224 KB
// ---------------------------------------------------------------------------
#define STG1 (APLANE + 2 * BSTG32)            // 81920 per stage
#define G1_BG16 (2 * STG1)                    // 163840
#define G1_BU16 (G1_BG16 + 2 * BPLANE)        // 196608
#define G1_TOTAL (G1_BU16 + 2 * BPLANE)       // 229376

__global__ __launch_bounds__(256, 1)
void gemm1_kernel(const float* __restrict__ Wg, const float* __restrict__ Wu,
                  const int* __restrict__ offs)
{
    extern __shared__ char smem[];
    const uint32_t sb = smem_u32(smem);
    const int tid  = threadIdx.x;
    const int wid  = tid >> 5;
    const int lane = tid & 31;
    const int wm   = wid & 3;
    const int wn   = wid >> 2;

    const int m0 = blockIdx.y * 128;
    const int n0 = blockIdx.x * 128;
    int e = 0;
    while (offs[e] <= m0) e++;

    const __half* A  = g_x16 + (size_t)m0 * H_DIM;
    const float*  Bg = Wg + (size_t)e * H_DIM * I_DIM;
    const float*  Bu = Wu + (size_t)e * H_DIM * I_DIM;

    auto prefetch = [&](int it) {
        uint32_t st = sb + (it & 1) * STG1;
        int k0 = it * 64;
        prefetch_a(A, H_DIM, k0, st, tid);
        prefetch_b32(Bg, I_DIM, k0, n0, st + APLANE, tid);
        prefetch_b32(Bu, I_DIM, k0, n0, st + APLANE + BSTG32, tid);
    };
    auto convert = [&](int it) {
        const char* stg = smem + (it & 1) * STG1 + APLANE;
        convert_b(stg,           smem + G1_BG16 + (it & 1) * BPLANE, tid);
        convert_b(stg + BSTG32,  smem + G1_BU16 + (it & 1) * BPLANE, tid);
    };

    float accg[2][8][4], accu[2][8][4];
    #pragma unroll
    for (int mf = 0; mf < 2; mf++)
        #pragma unroll
        for (int nf = 0; nf < 8; nf++)
            #pragma unroll
            for (int q = 0; q < 4; q++) { accg[mf][nf][q] = 0.f; accu[mf][nf][q] = 0.f; }

    prefetch(0); CP_COMMIT();
    prefetch(1); CP_COMMIT();
    CP_WAIT1();
    __syncthreads();
    convert(0);

    const int l16 = lane & 15;
    const int lhi = lane >> 4;
    const int NIT = H_DIM / 64;   // 32

    for (int it = 0; it < NIT; it++) {
        if (it + 1 < NIT) CP_WAIT0();     // stage(it+1) fp32 + A landed
        __syncthreads();
        // convert(it+1) overlaps MMA(it): disjoint smem buffers
        if (it + 1 < NIT) convert(it + 1);

        const uint32_t st  = sb + (it & 1) * STG1;
        const uint32_t bgb = sb + G1_BG16 + (it & 1) * BPLANE;
        const uint32_t bub = sb + G1_BU16 + (it & 1) * BPLANE;

        #pragma unroll
        for (int s = 0; s < 4; s++) {
            uint32_t a[2][4], bg[4][4], bu[4][4];
            #pragma unroll
            for (int mf = 0; mf < 2; mf++) {
                int row = wm * 32 + mf * 16 + l16;
                int ch  = 2 * s + lhi;
                ldsm4(a[mf], st + (uint32_t)(row * 128 + ((ch ^ (row & 7)) << 4)));
            }
            #pragma unroll
            for (int nf2 = 0; nf2 < 4; nf2++) {
                uint32_t off = b_off(s, wn * 64 + nf2 * 16, lane);
                ldsm4t(bg[nf2], bgb + off);
                ldsm4t(bu[nf2], bub + off);
            }
            #pragma unroll
            for (int mf = 0; mf < 2; mf++)
                #pragma unroll
                for (int nf = 0; nf < 8; nf++) {
                    const int n2 = nf >> 1, p = nf & 1;
                    mma16816(accg[mf][nf], a[mf], bg[n2][p], bg[n2][p + 2]);
                    mma16816(accu[mf][nf], a[mf], bu[n2][p], bu[n2][p + 2]);
                }
        }
        if (it + 2 < NIT) prefetch(it + 2);
        CP_COMMIT();
    }

    // Epilogue: h = silu(g) * u -> fp16
    const int quad = lane >> 2, tq = lane & 3;
    #pragma unroll
    for (int mf = 0; mf < 2; mf++)
        #pragma unroll
        for (int nf = 0; nf < 8; nf++)
            #pragma unroll
            for (int h = 0; h < 2; h++) {
                int m = m0 + wm * 32 + mf * 16 + quad + h * 8;
                int n = n0 + wn * 64 + nf * 8 + tq * 2;
                float g0 = accg[mf][nf][h * 2 + 0], u0 = accu[mf][nf][h * 2 + 0];
                float g1 = accg[mf][nf][h * 2 + 1], u1 = accu[mf][nf][h * 2 + 1];
                float h0 = (g0 / (1.0f + __expf(-g0))) * u0;
                float h1 = (g1 / (1.0f + __expf(-g1))) * u1;
                *reinterpret_cast<uint32_t*>(g_h16 + (size_t)m * I_DIM + n) = pkh2(h0, h1);
            }
}

// ---------------------------------------------------------------------------
// GEMM2: down proj with in-kernel weight convert.  out fp32.
// smem: 2 stages x (A16 16K | S32 32K) = 96K, then B16[2] 32K -> 128 KB
// ---------------------------------------------------------------------------
#define STG2 (APLANE + BSTG32)                // 49152 per stage
#define G2_B16 (2 * STG2)                     // 98304
#define G2_TOTAL (G2_B16 + 2 * BPLANE)        // 131072

__global__ __launch_bounds__(256, 1)
void gemm2_kernel(const float* __restrict__ Wd, const int* __restrict__ offs,
                  float* __restrict__ out)
{
    extern __shared__ char smem[];
    const uint32_t sb = smem_u32(smem);
    const int tid  = threadIdx.x;
    const int wid  = tid >> 5;
    const int lane = tid & 31;
    const int wm   = wid & 3;
    const int wn   = wid >> 2;

    const int m0 = blockIdx.y * 128;
    const int n0 = blockIdx.x * 128;
    int e = 0;
    while (offs[e] <= m0) e++;

    const __half* A = g_h16 + (size_t)m0 * I_DIM;
    const float*  B = Wd + (size_t)e * I_DIM * H_DIM;

    auto prefetch = [&](int it) {
        uint32_t st = sb + (it & 1) * STG2;
        int k0 = it * 64;
        prefetch_a(A, I_DIM, k0, st, tid);
        prefetch_b32(B, H_DIM, k0, n0, st + APLANE, tid);
    };
    auto convert = [&](int it) {
        convert_b(smem + (it & 1) * STG2 + APLANE,
                  smem + G2_B16 + (it & 1) * BPLANE, tid);
    };

    float acc[2][8][4];
    #pragma unroll
    for (int mf = 0; mf < 2; mf++)
        #pragma unroll
        for (int nf = 0; nf < 8; nf++)
            #pragma unroll
            for (int q = 0; q < 4; q++) acc[mf][nf][q] = 0.f;

    prefetch(0); CP_COMMIT();
    prefetch(1); CP_COMMIT();
    CP_WAIT1();
    __syncthreads();
    convert(0);

    const int l16 = lane & 15;
    const int lhi = lane >> 4;
    const int NIT = I_DIM / 64;   // 22

    for (int it = 0; it < NIT; it++) {
        if (it + 1 < NIT) CP_WAIT0();
        __syncthreads();
        if (it + 1 < NIT) convert(it + 1);

        const uint32_t st = sb + (it & 1) * STG2;
        const uint32_t bb = sb + G2_B16 + (it & 1) * BPLANE;

        #pragma unroll
        for (int s = 0; s < 4; s++) {
            uint32_t a[2][4], b[4][4];
            #pragma unroll
            for (int mf = 0; mf < 2; mf++) {
                int row = wm * 32 + mf * 16 + l16;
                int ch  = 2 * s + lhi;
                ldsm4(a[mf], st + (uint32_t)(row * 128 + ((ch ^ (row & 7)) << 4)));
            }
            #pragma unroll
            for (int nf2 = 0; nf2 < 4; nf2++)
                ldsm4t(b[nf2], bb + b_off(s, wn * 64 + nf2 * 16, lane));
            #pragma unroll
            for (int mf = 0; mf < 2; mf++)
                #pragma unroll
                for (int nf = 0; nf < 8; nf++) {
                    const int n2 = nf >> 1, p = nf & 1;
                    mma16816(acc[mf][nf], a[mf], b[n2][p], b[n2][p + 2]);
                }
        }
        if (it + 2 < NIT) prefetch(it + 2);
        CP_COMMIT();
    }

    const int quad = lane >> 2, tq = lane & 3;
    #pragma unroll
    for (int mf = 0; mf < 2; mf++)
        #pragma unroll
        for (int nf = 0; nf < 8; nf++)
            #pragma unroll
            for (int h = 0; h < 2; h++) {
                int m = m0 + wm * 32 + mf * 16 + quad + h * 8;
                int n = n0 + wn * 64 + nf * 8 + tq * 2;
                *reinterpret_cast<float2*>(out + (size_t)m * H_DIM + n) =
                    make_float2(acc[mf][nf][h * 2 + 0], acc[mf][nf][h * 2 + 1]);
            }
}

// ---------------------------------------------------------------------------
extern "C" void kernel_launch(void* const* d_in, const int* in_sizes, int n_in,
                              void* d_out, int out_size)
{
    const float* x    = (const float*)d_in[0];   // [T, H]
    const float* Wg   = (const float*)d_in[1];   // [E, H, I]
    const float* Wu   = (const float*)d_in[2];   // [E, H, I]
    const float* Wd   = (const float*)d_in[3];   // [E, I, H]
    const int*   offs = (const int*)  d_in[4];   // [E]
    float*       out  = (float*)d_out;           // [T, H]

    __half* x16;
    cudaGetSymbolAddress((void**)&x16, g_x16);

    cudaFuncSetAttribute(gemm1_kernel, cudaFuncAttributeMaxDynamicSharedMemorySize, G1_TOTAL);
    cudaFuncSetAttribute(gemm2_kernel, cudaFuncAttributeMaxDynamicSharedMemorySize, G2_TOTAL);

    // Convert only x up front; weights convert inside the GEMM k-loops.
    cvt_kernel<<<(int)(SZ_X / 2048), 256>>>(x, x16);

    gemm1_kernel<<<dim3(I_DIM / 128, T_TOK / 128), 256, G1_TOTAL>>>(Wg, Wu, offs);
    gemm2_kernel<<<dim3(H_DIM / 128, T_TOK / 128), 256, G2_TOTAL>>>(Wd, offs, out);
}

// round 6
// speedup vs baseline: 1.2505x; 1.2505x over previous
#include <cuda_runtime.h>
#include <cuda_fp16.h>
#include <cstdint>
#include <math.h>

// ---------------------------------------------------------------------------
// Problem dims (fixed)
// ---------------------------------------------------------------------------
#define T_TOK 8192
#define H_DIM 2048
#define I_DIM 1408
#define E_NUM 32

#define SZ_X ((size_t)T_TOK * H_DIM)
#define SZ_HH ((size_t)T_TOK * I_DIM)

// Scratch (device globals — no allocations allowed anywhere).
__device__ __align__(256) __half g_x16[SZ_X];    // [T][H] fp16
__device__ __align__(256) __half g_h16[SZ_HH];   // [T][I] fp16

// ---------------------------------------------------------------------------
// PTX helpers (base-target legal: cp.async / ldmatrix / mma.sync)
// ---------------------------------------------------------------------------
__device__ __forceinline__ uint32_t smem_u32(const void* p) {
    uint32_t a;
    asm("{ .reg .u64 t; cvta.to.shared.u64 t, %1; cvt.u32.u64 %0, t; }"
        : "=r"(a) : "l"(p));
    return a;
}
__device__ __forceinline__ void cpa16(uint32_t s, const void* g) {
    asm volatile("cp.async.cg.shared.global [%0], [%1], 16;" :: "r"(s), "l"(g));
}
#define CP_COMMIT() asm volatile("cp.async.commit_group;" ::: "memory")
#define CP_WAIT2()  asm volatile("cp.async.wait_group 2;" ::: "memory")
#define CP_WAIT3()  asm volatile("cp.async.wait_group 3;" ::: "memory")

__device__ __forceinline__ void ldsm4(uint32_t* r, uint32_t addr) {
    asm volatile("ldmatrix.sync.aligned.m8n8.x4.shared.b16 {%0,%1,%2,%3}, [%4];"
                 : "=r"(r[0]), "=r"(r[1]), "=r"(r[2]), "=r"(r[3]) : "r"(addr));
}
__device__ __forceinline__ void ldsm4t(uint32_t* r, uint32_t addr) {
    asm volatile("ldmatrix.sync.aligned.m8n8.x4.trans.shared.b16 {%0,%1,%2,%3}, [%4];"
                 : "=r"(r[0]), "=r"(r[1]), "=r"(r[2]), "=r"(r[3]) : "r"(addr));
}
__device__ __forceinline__ void mma16816(float* d, const uint32_t* a,
                                         uint32_t b0, uint32_t b1) {
    asm volatile(
        "mma.sync.aligned.m16n8k16.row.col.f32.f16.f16.f32 "
        "{%0,%1,%2,%3}, {%4,%5,%6,%7}, {%8,%9}, {%0,%1,%2,%3};"
        : "+f"(d[0]), "+f"(d[1]), "+f"(d[2]), "+f"(d[3])
        : "r"(a[0]), "r"(a[1]), "r"(a[2]), "r"(a[3]), "r"(b0), "r"(b1));
}
__device__ __forceinline__ uint32_t pkh2(float a, float b) {
    __half2 h = __floats2half2_rn(a, b);
    return *reinterpret_cast<uint32_t*>(&h);
}

// ---------------------------------------------------------------------------
// Prologue: fp32 -> fp16 for x only (weights convert inside the GEMMs)
// ---------------------------------------------------------------------------
__global__ __launch_bounds__(256)
void cvt_kernel(const float* __restrict__ src, __half* __restrict__ dst)
{
    size_t i = ((size_t)blockIdx.x * 256 + threadIdx.x) * 8;
    float4 v0 = *reinterpret_cast<const float4*>(src + i);
    float4 v1 = *reinterpret_cast<const float4*>(src + i + 4);
    uint4 o;
    o.x = pkh2(v0.x, v0.y);
    o.y = pkh2(v0.z, v0.w);
    o.z = pkh2(v1.x, v1.y);
    o.w = pkh2(v1.z, v1.w);
    *reinterpret_cast<uint4*>(dst + i) = o;
}

// ---------------------------------------------------------------------------
// Tile machinery (CTA 128x128, BK=64, 8 warps = 4m x 2n, warp 32x64)
// A: fp16 [M,K] k-contig; cp.async into SW128-swizzled fp16 plane (own group).
// B: fp32 [K,N] n-contig (native); cp.async into linear fp32 staging (own
//    group), converted in-smem to SW128 fp16 plane one iter ahead of use.
// ---------------------------------------------------------------------------
#define APLANE 16384      // 128 x 64 fp16
#define BSTG32 32768      // 64 x 128 fp32 staging
#define BPLANE 16384      // 64 x 128 fp16 (two 64-n halves of 8KB)

__device__ __forceinline__ void prefetch_a(const __half* A, int K, int k0,
                                           uint32_t st, int tid) {
    #pragma unroll
    for (int p = 0; p < 4; p++) {
        int c   = tid + 256 * p;          // 0..1023
        int row = c >> 3;                 // m 0..127
        int kc  = c & 7;
        uint32_t so = (uint32_t)(row * 128 + ((kc ^ (row & 7)) << 4));
        cpa16(st + so, A + (size_t)row * K + k0 + kc * 8);
    }
}
__device__ __forceinline__ void prefetch_b32(const float* B, int N, int k0,
                                             int n0, uint32_t st, int tid) {
    #pragma unroll
    for (int p = 0; p < 8; p++) {
        int c   = p * 256 + tid;          // 0..2047
        int row = c >> 5;                 // k 0..63
        int ch  = c & 31;                 // 16B chunk (4 floats)
        cpa16(st + (uint32_t)(row * 512 + ch * 16),
              B + (size_t)(k0 + row) * N + n0 + ch * 4);
    }
}
// In-smem convert: fp32 staging -> SW128 fp16 plane (verified in R5)
__device__ __forceinline__ void convert_b(const char* stg, char* dst, int tid) {
    #pragma unroll
    for (int p = 0; p < 8; p++) {
        int c = p * 256 + tid;            // float4 index 0..2047
        int r = c >> 5;                   // k row
        int n = (c & 31) * 4;             // n col (mult of 4)
        float4 v = *reinterpret_cast<const float4*>(stg + c * 16);
        int half = n >> 6;
        int jj   = (n & 63) >> 3;
        uint32_t off = (uint32_t)(half * 8192 + r * 128 +
                                  ((jj ^ (r & 7)) << 4) + (n & 4) * 2);
        *reinterpret_cast<uint2*>(dst + off) =
            make_uint2(pkh2(v.x, v.y), pkh2(v.z, v.w));
    }
}
// B fragment smem offset (within one fp16 BPLANE) — verified R4/R5.
__device__ __forceinline__ uint32_t b_off(int s, int base_n, int lane) {
    int kRow = s * 16 + (lane & 7) + ((lane >> 4) << 3);
    int nOff = base_n + (((lane >> 3) & 1) << 3);
    int half = nOff >> 6;
    int jj   = (nOff & 63) >> 3;
    return (uint32_t)(half * 8192 + kRow * 128 + ((jj ^ (kRow & 7)) << 4));
}

// ---------------------------------------------------------------------------
// GEMM1: fused gate+up with in-kernel weight convert.
// smem: 2 x (A 16K + 2 x B32 32K) = 160K + Bg16[2] 32K + Bu16[2] 32K = 224 KB
//
// Pipeline per iter (groups: B-prefetch and A-prefetch committed separately):
//   s1: pB(it+2), commit        s2: wait_group 2   (A(it), B32(it+1) landed)
//   s3: barrier                 s4: convert(it+1)  (overlaps s5 via ILP)
//   s5: MMA(it)                 s6: barrier; pA(it+2), commit
// Every group gets >= 1 full MMA iter in flight before its wait.
// ---------------------------------------------------------------------------
#define STG1 (APLANE + 2 * BSTG32)            // 81920 per stage
#define G1_BG16 (2 * STG1)                    // 163840
#define G1_BU16 (G1_BG16 + 2 * BPLANE)        // 196608
#define G1_TOTAL (G1_BU16 + 2 * BPLANE)       // 229376

__global__ __launch_bounds__(256, 1)
void gemm1_kernel(const float* __restrict__ Wg, const float* __restrict__ Wu,
                  const int* __restrict__ offs)
{
    extern __shared__ char smem[];
    const uint32_t sb = smem_u32(smem);
    const int tid  = threadIdx.x;
    const int wid  = tid >> 5;
    const int lane = tid & 31;
    const int wm   = wid & 3;
    const int wn   = wid >> 2;

    const int m0 = blockIdx.y * 128;
    const int n0 = blockIdx.x * 128;
    int e = 0;
    while (offs[e] <= m0) e++;

    const __half* A  = g_x16 + (size_t)m0 * H_DIM;
    const float*  Bg = Wg + (size_t)e * H_DIM * I_DIM;
    const float*  Bu = Wu + (size_t)e * H_DIM * I_DIM;

    auto pA = [&](int it) {
        prefetch_a(A, H_DIM, it * 64, sb + (it & 1) * STG1, tid);
    };
    auto pB = [&](int it) {
        uint32_t st = sb + (it & 1) * STG1;
        prefetch_b32(Bg, I_DIM, it * 64, n0, st + APLANE, tid);
        prefetch_b32(Bu, I_DIM, it * 64, n0, st + APLANE + BSTG32, tid);
    };
    auto convert = [&](int it) {
        const char* stg = smem + (it & 1) * STG1 + APLANE;
        convert_b(stg,          smem + G1_BG16 + (it & 1) * BPLANE, tid);
        convert_b(stg + BSTG32, smem + G1_BU16 + (it & 1) * BPLANE, tid);
    };

    float accg[2][8][4], accu[2][8][4];
    #pragma unroll
    for (int mf = 0; mf < 2; mf++)
        #pragma unroll
        for (int nf = 0; nf < 8; nf++)
            #pragma unroll
            for (int q = 0; q < 4; q++) { accg[mf][nf][q] = 0.f; accu[mf][nf][q] = 0.f; }

    // Pre-loop: groups B0, A0, B1, A1
    pB(0); CP_COMMIT();
    pA(0); CP_COMMIT();
    pB(1); CP_COMMIT();
    pA(1); CP_COMMIT();
    CP_WAIT3();                 // B0 landed
    __syncthreads();
    convert(0);

    const int l16 = lane & 15;
    const int lhi = lane >> 4;
    const int NIT = H_DIM / 64;   // 32

    for (int it = 0; it < NIT; it++) {
        if (it + 2 < NIT) pB(it + 2);
        CP_COMMIT();
        CP_WAIT2();             // A(it) + B32(it+1) done; A(it+1), B(it+2) in flight
        __syncthreads();
        if (it + 1 < NIT) convert(it + 1);

        const uint32_t st  = sb + (it & 1) * STG1;
        const uint32_t bgb = sb + G1_BG16 + (it & 1) * BPLANE;
        const uint32_t bub = sb + G1_BU16 + (it & 1) * BPLANE;

        #pragma unroll
        for (int s = 0; s < 4; s++) {
            uint32_t a[2][4], bg[4][4], bu[4][4];
            #pragma unroll
            for (int mf = 0; mf < 2; mf++) {
                int row = wm * 32 + mf * 16 + l16;
                int ch  = 2 * s + lhi;
                ldsm4(a[mf], st + (uint32_t)(row * 128 + ((ch ^ (row & 7)) << 4)));
            }
            #pragma unroll
            for (int nf2 = 0; nf2 < 4; nf2++) {
                uint32_t off = b_off(s, wn * 64 + nf2 * 16, lane);
                ldsm4t(bg[nf2], bgb + off);
                ldsm4t(bu[nf2], bub + off);
            }
            #pragma unroll
            for (int mf = 0; mf < 2; mf++)
                #pragma unroll
                for (int nf = 0; nf < 8; nf++) {
                    const int n2 = nf >> 1, p = nf & 1;
                    mma16816(accg[mf][nf], a[mf], bg[n2][p], bg[n2][p + 2]);
                    mma16816(accu[mf][nf], a[mf], bu[n2][p], bu[n2][p + 2]);
                }
        }
        __syncthreads();        // A(it) fully consumed by all warps
        if (it + 2 < NIT) pA(it + 2);
        CP_COMMIT();
    }

    // Epilogue: h = silu(g) * u -> fp16
    const int quad = lane >> 2, tq = lane & 3;
    #pragma unroll
    for (int mf = 0; mf < 2; mf++)
        #pragma unroll
        for (int nf = 0; nf < 8; nf++)
            #pragma unroll
            for (int h = 0; h < 2; h++) {
                int m = m0 + wm * 32 + mf * 16 + quad + h * 8;
                int n = n0 + wn * 64 + nf * 8 + tq * 2;
                float g0 = accg[mf][nf][h * 2 + 0], u0 = accu[mf][nf][h * 2 + 0];
                float g1 = accg[mf][nf][h * 2 + 1], u1 = accu[mf][nf][h * 2 + 1];
                float h0 = (g0 / (1.0f + __expf(-g0))) * u0;
                float h1 = (g1 / (1.0f + __expf(-g1))) * u1;
                *reinterpret_cast<uint32_t*>(g_h16 + (size_t)m * I_DIM + n) = pkh2(h0, h1);
            }
}

// ---------------------------------------------------------------------------
// GEMM2: down proj with in-kernel weight convert.  out fp32.
// smem: 2 x (A 16K + B32 32K) = 96K + B16[2] 32K = 128 KB
// ---------------------------------------------------------------------------
#define STG2 (APLANE + BSTG32)                // 49152 per stage
#define G2_B16 (2 * STG2)                     // 98304
#define G2_TOTAL (G2_B16 + 2 * BPLANE)        // 131072

__global__ __launch_bounds__(256, 1)
void gemm2_kernel(const float* __restrict__ Wd, const int* __restrict__ offs,
                  float* __restrict__ out)
{
    extern __shared__ char smem[];
    const uint32_t sb = smem_u32(smem);
    const int tid  = threadIdx.x;
    const int wid  = tid >> 5;
    const int lane = tid & 31;
    const int wm   = wid & 3;
    const int wn   = wid >> 2;

    const int m0 = blockIdx.y * 128;
    const int n0 = blockIdx.x * 128;
    int e = 0;
    while (offs[e] <= m0) e++;

    const __half* A = g_h16 + (size_t)m0 * I_DIM;
    const float*  B = Wd + (size_t)e * I_DIM * H_DIM;

    auto pA = [&](int it) {
        prefetch_a(A, I_DIM, it * 64, sb + (it & 1) * STG2, tid);
    };
    auto pB = [&](int it) {
        prefetch_b32(B, H_DIM, it * 64, n0, sb + (it & 1) * STG2 + APLANE, tid);
    };
    auto convert = [&](int it) {
        convert_b(smem + (it & 1) * STG2 + APLANE,
                  smem + G2_B16 + (it & 1) * BPLANE, tid);
    };

    float acc[2][8][4];
    #pragma unroll
    for (int mf = 0; mf < 2; mf++)
        #pragma unroll
        for (int nf = 0; nf < 8; nf++)
            #pragma unroll
            for (int q = 0; q < 4; q++) acc[mf][nf][q] = 0.f;

    pB(0); CP_COMMIT();
    pA(0); CP_COMMIT();
    pB(1); CP_COMMIT();
    pA(1); CP_COMMIT();
    CP_WAIT3();
    __syncthreads();
    convert(0);

    const int l16 = lane & 15;
    const int lhi = lane >> 4;
    const int NIT = I_DIM / 64;   // 22

    for (int it = 0; it < NIT; it++) {
        if (it + 2 < NIT) pB(it + 2);
        CP_COMMIT();
        CP_WAIT2();
        __syncthreads();
        if (it + 1 < NIT) convert(it + 1);

        const uint32_t st = sb + (it & 1) * STG2;
        const uint32_t bb = sb + G2_B16 + (it & 1) * BPLANE;

        #pragma unroll
        for (int s = 0; s < 4; s++) {
            uint32_t a[2][4], b[4][4];
            #pragma unroll
            for (int mf = 0; mf < 2; mf++) {
                int row = wm * 32 + mf * 16 + l16;
                int ch  = 2 * s + lhi;
                ldsm4(a[mf], st + (uint32_t)(row * 128 + ((ch ^ (row & 7)) << 4)));
            }
            #pragma unroll
            for (int nf2 = 0; nf2 < 4; nf2++)
                ldsm4t(b[nf2], bb + b_off(s, wn * 64 + nf2 * 16, lane));
            #pragma unroll
            for (int mf = 0; mf < 2; mf++)
                #pragma unroll
                for (int nf = 0; nf < 8; nf++) {
                    const int n2 = nf >> 1, p = nf & 1;
                    mma16816(acc[mf][nf], a[mf], b[n2][p], b[n2][p + 2]);
                }
        }
        __syncthreads();
        if (it + 2 < NIT) pA(it + 2);
        CP_COMMIT();
    }

    const int quad = lane >> 2, tq = lane & 3;
    #pragma unroll
    for (int mf = 0; mf < 2; mf++)
        #pragma unroll
        for (int nf = 0; nf < 8; nf++)
            #pragma unroll
            for (int h = 0; h < 2; h++) {
                int m = m0 + wm * 32 + mf * 16 + quad + h * 8;
                int n = n0 + wn * 64 + nf * 8 + tq * 2;
                *reinterpret_cast<float2*>(out + (size_t)m * H_DIM + n) =
                    make_float2(acc[mf][nf][h * 2 + 0], acc[mf][nf][h * 2 + 1]);
            }
}

// ---------------------------------------------------------------------------
extern "C" void kernel_launch(void* const* d_in, const int* in_sizes, int n_in,
                              void* d_out, int out_size)
{
    const float* x    = (const float*)d_in[0];   // [T, H]
    const float* Wg   = (const float*)d_in[1];   // [E, H, I]
    const float* Wu   = (const float*)d_in[2];   // [E, H, I]
    const float* Wd   = (const float*)d_in[3];   // [E, I, H]
    const int*   offs = (const int*)  d_in[4];   // [E]
    float*       out  = (float*)d_out;           // [T, H]

    __half* x16;
    cudaGetSymbolAddress((void**)&x16, g_x16);

    cudaFuncSetAttribute(gemm1_kernel, cudaFuncAttributeMaxDynamicSharedMemorySize, G1_TOTAL);
    cudaFuncSetAttribute(gemm2_kernel, cudaFuncAttributeMaxDynamicSharedMemorySize, G2_TOTAL);

    // Convert only x up front; weights convert inside the GEMM k-loops.
    cvt_kernel<<<(int)(SZ_X / 2048), 256>>>(x, x16);

    gemm1_kernel<<<dim3(I_DIM / 128, T_TOK / 128), 256, G1_TOTAL>>>(Wg, Wu, offs);
    gemm2_kernel<<<dim3(H_DIM / 128, T_TOK / 128), 256, G2_TOTAL>>>(Wd, offs, out);
}

// round 7
// speedup vs baseline: 1.4239x; 1.1387x over previous
#include <cuda_runtime.h>
#include <cuda_fp16.h>
#include <cstdint>
#include <math.h>

// ---------------------------------------------------------------------------
// Problem dims (fixed)
// ---------------------------------------------------------------------------
#define T_TOK 8192
#define H_DIM 2048
#define I_DIM 1408
#define E_NUM 32

#define SZ_X ((size_t)T_TOK * H_DIM)
#define SZ_HH ((size_t)T_TOK * I_DIM)

// Scratch (device globals — no allocations allowed anywhere).
__device__ __align__(256) __half g_x16[SZ_X];    // [T][H] fp16
__device__ __align__(256) __half g_h16[SZ_HH];   // [T][I] fp16

// ---------------------------------------------------------------------------
// PTX helpers (base-target legal: cp.async / ldmatrix / mma.sync)
// ---------------------------------------------------------------------------
__device__ __forceinline__ uint32_t smem_u32(const void* p) {
    uint32_t a;
    asm("{ .reg .u64 t; cvta.to.shared.u64 t, %1; cvt.u32.u64 %0, t; }"
        : "=r"(a) : "l"(p));
    return a;
}
__device__ __forceinline__ void cpa16(uint32_t s, const void* g) {
    asm volatile("cp.async.cg.shared.global [%0], [%1], 16;" :: "r"(s), "l"(g));
}
#define CP_COMMIT() asm volatile("cp.async.commit_group;" ::: "memory")
#define CP_WAIT1()  asm volatile("cp.async.wait_group 1;" ::: "memory")

__device__ __forceinline__ void ldsm4(uint32_t* r, uint32_t addr) {
    asm volatile("ldmatrix.sync.aligned.m8n8.x4.shared.b16 {%0,%1,%2,%3}, [%4];"
                 : "=r"(r[0]), "=r"(r[1]), "=r"(r[2]), "=r"(r[3]) : "r"(addr));
}
__device__ __forceinline__ void ldsm4t(uint32_t* r, uint32_t addr) {
    asm volatile("ldmatrix.sync.aligned.m8n8.x4.trans.shared.b16 {%0,%1,%2,%3}, [%4];"
                 : "=r"(r[0]), "=r"(r[1]), "=r"(r[2]), "=r"(r[3]) : "r"(addr));
}
__device__ __forceinline__ void mma16816(float* d, const uint32_t* a,
                                         uint32_t b0, uint32_t b1) {
    asm volatile(
        "mma.sync.aligned.m16n8k16.row.col.f32.f16.f16.f32 "
        "{%0,%1,%2,%3}, {%4,%5,%6,%7}, {%8,%9}, {%0,%1,%2,%3};"
        : "+f"(d[0]), "+f"(d[1]), "+f"(d[2]), "+f"(d[3])
        : "r"(a[0]), "r"(a[1]), "r"(a[2]), "r"(a[3]), "r"(b0), "r"(b1));
}
__device__ __forceinline__ uint32_t pkh2(float a, float b) {
    __half2 h = __floats2half2_rn(a, b);
    return *reinterpret_cast<uint32_t*>(&h);
}

// ---------------------------------------------------------------------------
// Prologue: fp32 -> fp16 for x only (weights convert inside the GEMMs)
// ---------------------------------------------------------------------------
__global__ __launch_bounds__(256)
void cvt_kernel(const float* __restrict__ src, __half* __restrict__ dst)
{
    size_t i = ((size_t)blockIdx.x * 256 + threadIdx.x) * 8;
    float4 v0 = *reinterpret_cast<const float4*>(src + i);
    float4 v1 = *reinterpret_cast<const float4*>(src + i + 4);
    uint4 o;
    o.x = pkh2(v0.x, v0.y);
    o.y = pkh2(v0.z, v0.w);
    o.z = pkh2(v1.x, v1.y);
    o.w = pkh2(v1.z, v1.w);
    *reinterpret_cast<uint4*>(dst + i) = o;
}

// ---------------------------------------------------------------------------
// Tile machinery (CTA 128x128, BK=64, 8 warps = 4m x 2n, warp 32x64)
// A: fp16 [M,K] k-contig; cp.async into SW128-swizzled fp16 plane.
// B: fp32 [K,N] n-contig (native); LDG.128 -> registers -> fp16 convert ->
//    STS into SW128 fp16 plane.  No fp32 smem staging (crossbar relief).
// ---------------------------------------------------------------------------
#define APLANE 16384      // 128 x 64 fp16
#define BPLANE 16384      // 64 x 128 fp16 (two 64-n halves of 8KB)

__device__ __forceinline__ void prefetch_a(const __half* A, int K, int k0,
                                           uint32_t st, int tid) {
    #pragma unroll
    for (int p = 0; p < 4; p++) {
        int c   = tid + 256 * p;          // 0..1023
        int row = c >> 3;                 // m 0..127
        int kc  = c & 7;
        uint32_t so = (uint32_t)(row * 128 + ((kc ^ (row & 7)) << 4));
        cpa16(st + so, A + (size_t)row * K + k0 + kc * 8);
    }
}
// LDG one k32 half of a 64x128 fp32 B tile into 4 float4 regs (coalesced).
__device__ __forceinline__ void ldg_bhalf(const float* B, int N, int k0, int n0,
                                          int tid, int h, float4* r) {
    #pragma unroll
    for (int p = 0; p < 4; p++) {
        int c   = (h * 4 + p) * 256 + tid;   // chunk 0..2047
        int row = c >> 5;                    // k 0..63
        int ch  = c & 31;                    // 16B chunk in n
        r[p] = __ldg(reinterpret_cast<const float4*>(
                     B + (size_t)(k0 + row) * N + n0 + ch * 4));
    }
}
// Convert regs -> SW128 fp16 plane (same mapping as R5/R6 convert_b).
__device__ __forceinline__ void sts_bhalf(const float4* r, char* dst, int tid, int h) {
    #pragma unroll
    for (int p = 0; p < 4; p++) {
        int c   = (h * 4 + p) * 256 + tid;
        int row = c >> 5;
        int n   = (c & 31) * 4;
        int hf  = n >> 6;
        int jj  = (n & 63) >> 3;
        uint32_t off = (uint32_t)(hf * 8192 + row * 128 +
                                  ((jj ^ (row & 7)) << 4) + (n & 4) * 2);
        *reinterpret_cast<uint2*>(dst + off) =
            make_uint2(pkh2(r[p].x, r[p].y), pkh2(r[p].z, r[p].w));
    }
}
// B fragment smem offset (within one fp16 BPLANE) — verified R4-R6.
__device__ __forceinline__ uint32_t b_off(int s, int base_n, int lane) {
    int kRow = s * 16 + (lane & 7) + ((lane >> 4) << 3);
    int nOff = base_n + (((lane >> 3) & 1) << 3);
    int half = nOff >> 6;
    int jj   = (nOff & 63) >> 3;
    return (uint32_t)(half * 8192 + kRow * 128 + ((jj ^ (kRow & 7)) << 4));
}

// ---------------------------------------------------------------------------
// GEMM1: fused gate+up, in-register weight convert.
// smem: A[2] 32K + Bg16[2] 32K + Bu16[2] 32K = 96 KB
// ---------------------------------------------------------------------------
#define G1_A(s)  ((s) * APLANE)
#define G1_BG(s) (2 * APLANE + (s) * BPLANE)
#define G1_BU(s) (2 * APLANE + 2 * BPLANE + (s) * BPLANE)
#define G1_TOTAL (2 * APLANE + 4 * BPLANE)    // 98304

__global__ __launch_bounds__(256, 1)
void gemm1_kernel(const float* __restrict__ Wg, const float* __restrict__ Wu,
                  const int* __restrict__ offs)
{
    extern __shared__ char smem[];
    const uint32_t sb = smem_u32(smem);
    const int tid  = threadIdx.x;
    const int wid  = tid >> 5;
    const int lane = tid & 31;
    const int wm   = wid & 3;
    const int wn   = wid >> 2;

    const int m0 = blockIdx.y * 128;
    const int n0 = blockIdx.x * 128;
    int e = 0;
    while (offs[e] <= m0) e++;

    const __half* A  = g_x16 + (size_t)m0 * H_DIM;
    const float*  Bg = Wg + (size_t)e * H_DIM * I_DIM;
    const float*  Bu = Wu + (size_t)e * H_DIM * I_DIM;

    float accg[2][8][4], accu[2][8][4];
    #pragma unroll
    for (int mf = 0; mf < 2; mf++)
        #pragma unroll
        for (int nf = 0; nf < 8; nf++)
            #pragma unroll
            for (int q = 0; q < 4; q++) { accg[mf][nf][q] = 0.f; accu[mf][nf][q] = 0.f; }

    // Prologue: A(0), A(1) in flight; B16(0) built from registers.
    prefetch_a(A, H_DIM, 0, sb + G1_A(0), tid);  CP_COMMIT();
    prefetch_a(A, H_DIM, 64, sb + G1_A(1), tid); CP_COMMIT();
    {
        float4 rg[4], ru[4];
        #pragma unroll
        for (int h = 0; h < 2; h++) {
            ldg_bhalf(Bg, I_DIM, 0, n0, tid, h, rg);
            ldg_bhalf(Bu, I_DIM, 0, n0, tid, h, ru);
            sts_bhalf(rg, smem + G1_BG(0), tid, h);
            sts_bhalf(ru, smem + G1_BU(0), tid, h);
        }
    }

    const int l16 = lane & 15;
    const int lhi = lane >> 4;
    const int NIT = H_DIM / 64;   // 32

    for (int it = 0; it < NIT; it++) {
        CP_WAIT1();              // A(it) landed (A(it+1) may remain in flight)
        __syncthreads();         // B16(it) stores + A(it) visible to all

        const int sp  = it & 1;
        const int spn = 1 - sp;
        const uint32_t stA = sb + G1_A(sp);
        const uint32_t bgb = sb + G1_BG(sp);
        const uint32_t bub = sb + G1_BU(sp);
        const bool more = (it + 1 < NIT);

        float4 rg[4], ru[4];
        if (more) {              // LDG half0 of B(it+1): consumed after s=1
            ldg_bhalf(Bg, I_DIM, (it + 1) * 64, n0, tid, 0, rg);
            ldg_bhalf(Bu, I_DIM, (it + 1) * 64, n0, tid, 0, ru);
        }

        #pragma unroll
        for (int s = 0; s < 2; s++) {
            uint32_t a[2][4], bg[4][4], bu[4][4];
            #pragma unroll
            for (int mf = 0; mf < 2; mf++) {
                int row = wm * 32 + mf * 16 + l16;
                int ch  = 2 * s + lhi;
                ldsm4(a[mf], stA + (uint32_t)(row * 128 + ((ch ^ (row & 7)) << 4)));
            }
            #pragma unroll
            for (int nf2 = 0; nf2 < 4; nf2++) {
                uint32_t off = b_off(s, wn * 64 + nf2 * 16, lane);
                ldsm4t(bg[nf2], bgb + off);
                ldsm4t(bu[nf2], bub + off);
            }
            #pragma unroll
            for (int mf = 0; mf < 2; mf++)
                #pragma unroll
                for (int nf = 0; nf < 8; nf++) {
                    const int n2 = nf >> 1, p = nf & 1;
                    mma16816(accg[mf][nf], a[mf], bg[n2][p], bg[n2][p + 2]);
                    mma16816(accu[mf][nf], a[mf], bu[n2][p], bu[n2][p + 2]);
                }
        }

        if (more) {              // store half0 (other plane), fetch half1
            sts_bhalf(rg, smem + G1_BG(spn), tid, 0);
            sts_bhalf(ru, smem + G1_BU(spn), tid, 0);
            ldg_bhalf(Bg, I_DIM, (it + 1) * 64, n0, tid, 1, rg);
            ldg_bhalf(Bu, I_DIM, (it + 1) * 64, n0, tid, 1, ru);
        }

        #pragma unroll
        for (int s = 2; s < 4; s++) {
            uint32_t a[2][4], bg[4][4], bu[4][4];
            #pragma unroll
            for (int mf = 0; mf < 2; mf++) {
                int row = wm * 32 + mf * 16 + l16;
                int ch  = 2 * s + lhi;
                ldsm4(a[mf], stA + (uint32_t)(row * 128 + ((ch ^ (row & 7)) << 4)));
            }
            #pragma unroll
            for (int nf2 = 0; nf2 < 4; nf2++) {
                uint32_t off = b_off(s, wn * 64 + nf2 * 16, lane);
                ldsm4t(bg[nf2], bgb + off);
                ldsm4t(bu[nf2], bub + off);
            }
            #pragma unroll
            for (int mf = 0; mf < 2; mf++)
                #pragma unroll
                for (int nf = 0; nf < 8; nf++) {
                    const int n2 = nf >> 1, p = nf & 1;
                    mma16816(accg[mf][nf], a[mf], bg[n2][p], bg[n2][p + 2]);
                    mma16816(accu[mf][nf], a[mf], bu[n2][p], bu[n2][p + 2]);
                }
        }

        if (more) {
            sts_bhalf(rg, smem + G1_BG(spn), tid, 1);
            sts_bhalf(ru, smem + G1_BU(spn), tid, 1);
        }
        __syncthreads();         // A(it) consumed by all warps; stage free
        if (it + 2 < NIT)
            prefetch_a(A, H_DIM, (it + 2) * 64, sb + G1_A(sp), tid);
        CP_COMMIT();
    }

    // Epilogue: h = silu(g) * u -> fp16
    const int quad = lane >> 2, tq = lane & 3;
    #pragma unroll
    for (int mf = 0; mf < 2; mf++)
        #pragma unroll
        for (int nf = 0; nf < 8; nf++)
            #pragma unroll
            for (int h = 0; h < 2; h++) {
                int m = m0 + wm * 32 + mf * 16 + quad + h * 8;
                int n = n0 + wn * 64 + nf * 8 + tq * 2;
                float g0 = accg[mf][nf][h * 2 + 0], u0 = accu[mf][nf][h * 2 + 0];
                float g1 = accg[mf][nf][h * 2 + 1], u1 = accu[mf][nf][h * 2 + 1];
                float h0 = (g0 / (1.0f + __expf(-g0))) * u0;
                float h1 = (g1 / (1.0f + __expf(-g1))) * u1;
                *reinterpret_cast<uint32_t*>(g_h16 + (size_t)m * I_DIM + n) = pkh2(h0, h1);
            }
}

// ---------------------------------------------------------------------------
// GEMM2: down proj, in-register weight convert.  out fp32.
// smem: A[2] 32K + B16[2] 32K = 64 KB -> 2 CTAs/SM
// ---------------------------------------------------------------------------
#define G2_A(s)  ((s) * APLANE)
#define G2_B(s)  (2 * APLANE + (s) * BPLANE)
#define G2_TOTAL (2 * APLANE + 2 * BPLANE)    // 65536

__global__ __launch_bounds__(256, 2)
void gemm2_kernel(const float* __restrict__ Wd, const int* __restrict__ offs,
                  float* __restrict__ out)
{
    extern __shared__ char smem[];
    const uint32_t sb = smem_u32(smem);
    const int tid  = threadIdx.x;
    const int wid  = tid >> 5;
    const int lane = tid & 31;
    const int wm   = wid & 3;
    const int wn   = wid >> 2;

    const int m0 = blockIdx.y * 128;
    const int n0 = blockIdx.x * 128;
    int e = 0;
    while (offs[e] <= m0) e++;

    const __half* A = g_h16 + (size_t)m0 * I_DIM;
    const float*  B = Wd + (size_t)e * I_DIM * H_DIM;

    float acc[2][8][4];
    #pragma unroll
    for (int mf = 0; mf < 2; mf++)
        #pragma unroll
        for (int nf = 0; nf < 8; nf++)
            #pragma unroll
            for (int q = 0; q < 4; q++) acc[mf][nf][q] = 0.f;

    prefetch_a(A, I_DIM, 0, sb + G2_A(0), tid);  CP_COMMIT();
    prefetch_a(A, I_DIM, 64, sb + G2_A(1), tid); CP_COMMIT();
    {
        float4 r[4];
        #pragma unroll
        for (int h = 0; h < 2; h++) {
            ldg_bhalf(B, H_DIM, 0, n0, tid, h, r);
            sts_bhalf(r, smem + G2_B(0), tid, h);
        }
    }

    const int l16 = lane & 15;
    const int lhi = lane >> 4;
    const int NIT = I_DIM / 64;   // 22

    for (int it = 0; it < NIT; it++) {
        CP_WAIT1();
        __syncthreads();

        const int sp  = it & 1;
        const int spn = 1 - sp;
        const uint32_t stA = sb + G2_A(sp);
        const uint32_t bb  = sb + G2_B(sp);
        const bool more = (it + 1 < NIT);

        float4 r[4];
        if (more) ldg_bhalf(B, H_DIM, (it + 1) * 64, n0, tid, 0, r);

        #pragma unroll
        for (int s = 0; s < 2; s++) {
            uint32_t a[2][4], b[4][4];
            #pragma unroll
            for (int mf = 0; mf < 2; mf++) {
                int row = wm * 32 + mf * 16 + l16;
                int ch  = 2 * s + lhi;
                ldsm4(a[mf], stA + (uint32_t)(row * 128 + ((ch ^ (row & 7)) << 4)));
            }
            #pragma unroll
            for (int nf2 = 0; nf2 < 4; nf2++)
                ldsm4t(b[nf2], bb + b_off(s, wn * 64 + nf2 * 16, lane));
            #pragma unroll
            for (int mf = 0; mf < 2; mf++)
                #pragma unroll
                for (int nf = 0; nf < 8; nf++) {
                    const int n2 = nf >> 1, p = nf & 1;
                    mma16816(acc[mf][nf], a[mf], b[n2][p], b[n2][p + 2]);
                }
        }

        if (more) {
            sts_bhalf(r, smem + G2_B(spn), tid, 0);
            ldg_bhalf(B, H_DIM, (it + 1) * 64, n0, tid, 1, r);
        }

        #pragma unroll
        for (int s = 2; s < 4; s++) {
            uint32_t a[2][4], b[4][4];
            #pragma unroll
            for (int mf = 0; mf < 2; mf++) {
                int row = wm * 32 + mf * 16 + l16;
                int ch  = 2 * s + lhi;
                ldsm4(a[mf], stA + (uint32_t)(row * 128 + ((ch ^ (row & 7)) << 4)));
            }
            #pragma unroll
            for (int nf2 = 0; nf2 < 4; nf2++)
                ldsm4t(b[nf2], bb + b_off(s, wn * 64 + nf2 * 16, lane));
            #pragma unroll
            for (int mf = 0; mf < 2; mf++)
                #pragma unroll
                for (int nf = 0; nf < 8; nf++) {
                    const int n2 = nf >> 1, p = nf & 1;
                    mma16816(acc[mf][nf], a[mf], b[n2][p], b[n2][p + 2]);
                }
        }

        if (more) sts_bhalf(r, smem + G2_B(spn), tid, 1);
        __syncthreads();
        if (it + 2 < NIT)
            prefetch_a(A, I_DIM, (it + 2) * 64, sb + G2_A(sp), tid);
        CP_COMMIT();
    }

    const int quad = lane >> 2, tq = lane & 3;
    #pragma unroll
    for (int mf = 0; mf < 2; mf++)
        #pragma unroll
        for (int nf = 0; nf < 8; nf++)
            #pragma unroll
            for (int h = 0; h < 2; h++) {
                int m = m0 + wm * 32 + mf * 16 + quad + h * 8;
                int n = n0 + wn * 64 + nf * 8 + tq * 2;
                *reinterpret_cast<float2*>(out + (size_t)m * H_DIM + n) =
                    make_float2(acc[mf][nf][h * 2 + 0], acc[mf][nf][h * 2 + 1]);
            }
}

// ---------------------------------------------------------------------------
extern "C" void kernel_launch(void* const* d_in, const int* in_sizes, int n_in,
                              void* d_out, int out_size)
{
    const float* x    = (const float*)d_in[0];   // [T, H]
    const float* Wg   = (const float*)d_in[1];   // [E, H, I]
    const float* Wu   = (const float*)d_in[2];   // [E, H, I]
    const float* Wd   = (const float*)d_in[3];   // [E, I, H]
    const int*   offs = (const int*)  d_in[4];   // [E]
    float*       out  = (float*)d_out;           // [T, H]

    __half* x16;
    cudaGetSymbolAddress((void**)&x16, g_x16);

    cudaFuncSetAttribute(gemm1_kernel, cudaFuncAttributeMaxDynamicSharedMemorySize, G1_TOTAL);
    cudaFuncSetAttribute(gemm2_kernel, cudaFuncAttributeMaxDynamicSharedMemorySize, G2_TOTAL);

    cvt_kernel<<<(int)(SZ_X / 2048), 256>>>(x, x16);

    gemm1_kernel<<<dim3(I_DIM / 128, T_TOK / 128), 256, G1_TOTAL>>>(Wg, Wu, offs);
    gemm2_kernel<<<dim3(H_DIM / 128, T_TOK / 128), 256, G2_TOTAL>>>(Wd, offs, out);
}